// round 3
// baseline (speedup 1.0000x reference)
#include <cuda_runtime.h>
#include <cstdint>

// GCN 2-layer: out = spmm(relu(spmm(X)@W1))@W2,  A_norm = D^-1/2 A D^-1/2
// N=50000, E=850000, D=64.
//
// R3 strategy:
//   1. Build CSR-by-dst once per launch (histogram -> scan -> bucket edges).
//   2. SPMM = register-accumulating gather per dst row (no atomics, write-once,
//      no pre-zero). Features prescaled by deg_inv_sqrt on the src side; dst
//      side folded into the GEMM epilogue (linearity).
//   3. GEMM 64x64 uses packed fma.rn.f32x2 (Blackwell FFMA2) to halve the
//      FFMA issue floor; 256 thr/CTA, 2row x 16col tiles, 3 CTAs/SM.

#define D 64
#define NMAX 50176
#define EMAX 1048576

__device__ float g_xs[NMAX * D];        // prescaled features (xs, then hs)
__device__ float g_agg[NMAX * D];       // aggregation result
__device__ int   g_deg[NMAX];
__device__ int   g_row[NMAX + 1];
__device__ int   g_cur[NMAX];
__device__ int   g_srt[EMAX];           // src ids sorted by dst
__device__ int   g_is64;

// ---------------------------------------------------------------------------
// f32x2 helpers (packed dual-FMA; ptxas never emits these from C++)
// ---------------------------------------------------------------------------
__device__ __forceinline__ unsigned long long pack2(float a) {
    unsigned long long r;
    asm("mov.b64 %0, {%1, %1};" : "=l"(r) : "f"(a));
    return r;
}
__device__ __forceinline__ void fma2(unsigned long long& acc,
                                     unsigned long long a, unsigned long long b) {
    asm("fma.rn.f32x2 %0, %1, %2, %0;" : "+l"(acc) : "l"(a), "l"(b));
}
__device__ __forceinline__ float2 unpack2(unsigned long long v) {
    float2 f;
    asm("mov.b64 {%0, %1}, %2;" : "=f"(f.x), "=f"(f.y) : "l"(v));
    return f;
}

// ---------------------------------------------------------------------------
// Edge dtype detection (int64 ids < 50000 -> zero high words)
// ---------------------------------------------------------------------------
__global__ void detect_kernel(const int* __restrict__ w) {
    if (threadIdx.x == 0) {
        int is64 = 1;
        #pragma unroll 1
        for (int i = 0; i < 64; i++)
            if (w[2 * i + 1] != 0) { is64 = 0; break; }
        g_is64 = is64;
    }
}

// ---------------------------------------------------------------------------
// CSR build: histogram of dst
// ---------------------------------------------------------------------------
__global__ void __launch_bounds__(256) hist_kernel(const void* __restrict__ ei, int E) {
    int e = blockIdx.x * 256 + threadIdx.x;
    if (e >= E) return;
    int d = g_is64 ? (int)((const long long*)ei)[E + e]
                   : ((const int*)ei)[E + e];
    atomicAdd(&g_deg[d], 1);
}

// ---------------------------------------------------------------------------
// CSR build: single-CTA exclusive scan of degrees -> row offsets + cursors
// ---------------------------------------------------------------------------
__global__ void __launch_bounds__(1024) scan_kernel(int N, int E) {
    __shared__ int sums[1024];
    int t = threadIdx.x;
    int chunk = (N + 1023) >> 10;
    int b = t * chunk;
    int eN = min(b + chunk, N);

    int s = 0;
    for (int i = b; i < eN; i++) s += g_deg[i];
    sums[t] = s;
    __syncthreads();

    // Hillis-Steele inclusive scan
    for (int off = 1; off < 1024; off <<= 1) {
        int v = (t >= off) ? sums[t - off] : 0;
        __syncthreads();
        sums[t] += v;
        __syncthreads();
    }

    int run = (t == 0) ? 0 : sums[t - 1];
    for (int i = b; i < eN; i++) {
        g_row[i] = run;
        g_cur[i] = run;
        run += g_deg[i];
    }
    if (t == 0) g_row[N] = E;
}

// ---------------------------------------------------------------------------
// CSR build: bucket src ids by dst
// ---------------------------------------------------------------------------
__global__ void __launch_bounds__(256) bucket_kernel(const void* __restrict__ ei, int E) {
    int e = blockIdx.x * 256 + threadIdx.x;
    if (e >= E) return;
    int s, d;
    if (g_is64) {
        const long long* p = (const long long*)ei;
        s = (int)p[e]; d = (int)p[E + e];
    } else {
        const int* p = (const int*)ei;
        s = p[e]; d = p[E + e];
    }
    int pos = atomicAdd(&g_cur[d], 1);
    g_srt[pos] = s;
}

// ---------------------------------------------------------------------------
// Prescale: xs[i,:] = dis[i] * x[i,:]
// ---------------------------------------------------------------------------
__global__ void __launch_bounds__(256) prescale_kernel(
    const float4* __restrict__ x, const float* __restrict__ dis,
    float4* __restrict__ xs, int n4)
{
    int i = blockIdx.x * 256 + threadIdx.x;
    if (i >= n4) return;
    float s = dis[i >> 4];
    float4 v = x[i];
    v.x *= s; v.y *= s; v.z *= s; v.w *= s;
    xs[i] = v;
}

// ---------------------------------------------------------------------------
// Gather-SPMM: agg[g,:] = sum over in-edges of feat[src,:]
// 16 threads per dst row, float4 per thread, register accumulation,
// single write per row (no pre-zero needed).
// ---------------------------------------------------------------------------
__global__ void __launch_bounds__(256) gather_kernel(
    const float4* __restrict__ feat,
    float4* __restrict__ out, int N)
{
    int idx = blockIdx.x * 256 + threadIdx.x;
    int g = idx >> 4;
    if (g >= N) return;
    int lane = idx & 15;

    int e   = g_row[g];
    int end = g_row[g + 1];

    float4 acc = make_float4(0.f, 0.f, 0.f, 0.f);

    for (; e + 3 < end; e += 4) {
        int s0 = g_srt[e], s1 = g_srt[e + 1], s2 = g_srt[e + 2], s3 = g_srt[e + 3];
        float4 a = feat[s0 * 16 + lane];
        float4 b = feat[s1 * 16 + lane];
        float4 c = feat[s2 * 16 + lane];
        float4 d = feat[s3 * 16 + lane];
        acc.x += (a.x + b.x) + (c.x + d.x);
        acc.y += (a.y + b.y) + (c.y + d.y);
        acc.z += (a.z + b.z) + (c.z + d.z);
        acc.w += (a.w + b.w) + (c.w + d.w);
    }
    for (; e < end; e++) {
        float4 a = feat[g_srt[e] * 16 + lane];
        acc.x += a.x; acc.y += a.y; acc.z += a.z; acc.w += a.w;
    }
    out[g * 16 + lane] = acc;
}

// ---------------------------------------------------------------------------
// GEMM: Y[r,:] = g(dis[r] * (X[r,:] @ W)),  W is 64x64.
//   mode 0: g(v) = v
//   mode 1: g(v) = relu(v) * dis[r]    (src-prescale for next scatter)
// 256 threads/CTA, 2 rows x 16 cols per thread, packed f32x2 FMA.
// ---------------------------------------------------------------------------
__global__ void __launch_bounds__(256, 3) gemm64_kernel(
    const float* __restrict__ X,
    const float* __restrict__ W,
    const float* __restrict__ dis,
    float*       __restrict__ Y,
    int n, int mode)
{
    __shared__ float Ws[64 * 64];
    #pragma unroll
    for (int i = threadIdx.x; i < 1024; i += 256)
        ((float4*)Ws)[i] = ((const float4*)W)[i];
    __syncthreads();

    int rg = threadIdx.x >> 2;          // 0..63
    int cg = (threadIdx.x & 3) << 4;    // 0,16,32,48
    int r0 = blockIdx.x * 128 + (rg << 1);

    unsigned long long acc[2][8];
    #pragma unroll
    for (int i = 0; i < 2; i++)
        #pragma unroll
        for (int j = 0; j < 8; j++)
            acc[i][j] = 0ULL;

    const float4* X4 = (const float4*)X;

    #pragma unroll 4
    for (int k4 = 0; k4 < 16; k4++) {
        float4 xv0 = (r0     < n) ? X4[ r0      * 16 + k4] : make_float4(0.f,0.f,0.f,0.f);
        float4 xv1 = (r0 + 1 < n) ? X4[(r0 + 1) * 16 + k4] : make_float4(0.f,0.f,0.f,0.f);
        #pragma unroll
        for (int kk = 0; kk < 4; kk++) {
            const unsigned long long* wrow =
                (const unsigned long long*)&Ws[(k4 * 4 + kk) * 64 + cg];
            float x0 = (kk == 0) ? xv0.x : (kk == 1) ? xv0.y : (kk == 2) ? xv0.z : xv0.w;
            float x1 = (kk == 0) ? xv1.x : (kk == 1) ? xv1.y : (kk == 2) ? xv1.z : xv1.w;
            unsigned long long p0 = pack2(x0);
            unsigned long long p1 = pack2(x1);
            #pragma unroll
            for (int j = 0; j < 8; j++) {
                unsigned long long w = wrow[j];
                fma2(acc[0][j], p0, w);
                fma2(acc[1][j], p1, w);
            }
        }
    }

    #pragma unroll
    for (int i = 0; i < 2; i++) {
        int r = r0 + i;
        if (r < n) {
            float s = dis[r];
            float* yo = &Y[r * 64 + cg];
            #pragma unroll
            for (int j4 = 0; j4 < 4; j4++) {
                float2 lo = unpack2(acc[i][j4 * 2]);
                float2 hi = unpack2(acc[i][j4 * 2 + 1]);
                float4 o;
                o.x = lo.x * s; o.y = lo.y * s;
                o.z = hi.x * s; o.w = hi.y * s;
                if (mode) {
                    o.x = fmaxf(o.x, 0.f) * s; o.y = fmaxf(o.y, 0.f) * s;
                    o.z = fmaxf(o.z, 0.f) * s; o.w = fmaxf(o.w, 0.f) * s;
                }
                *(float4*)(yo + j4 * 4) = o;
            }
        }
    }
}

// ---------------------------------------------------------------------------
// Launch
// ---------------------------------------------------------------------------
extern "C" void kernel_launch(void* const* d_in, const int* in_sizes, int n_in,
                              void* d_out, int out_size)
{
    const float* x   = (const float*)d_in[0];
    const void*  ei  = d_in[1];
    const float* dis = (const float*)d_in[2];
    const float* W1  = (const float*)d_in[n_in - 2];
    const float* W2  = (const float*)d_in[n_in - 1];

    int N = in_sizes[0] / D;
    int E = in_sizes[1] / 2;

    float* xs  = nullptr; float* agg = nullptr; int* deg = nullptr;
    cudaGetSymbolAddress((void**)&xs,  g_xs);
    cudaGetSymbolAddress((void**)&agg, g_agg);
    cudaGetSymbolAddress((void**)&deg, g_deg);

    int n4     = N * (D / 4);
    int pgrid  = (n4 + 255) / 256;
    int egrid  = (E + 255) / 256;
    int ggrid  = (N * 16 + 255) / 256;
    int mgrid  = (N + 127) / 128;

    // CSR build (shared by both layers)
    detect_kernel<<<1, 32>>>((const int*)ei);
    cudaMemsetAsync(deg, 0, (size_t)N * sizeof(int));
    hist_kernel<<<egrid, 256>>>(ei, E);
    scan_kernel<<<1, 1024>>>(N, E);
    bucket_kernel<<<egrid, 256>>>(ei, E);

    // Layer 1
    prescale_kernel<<<pgrid, 256>>>((const float4*)x, dis, (float4*)xs, n4);
    gather_kernel<<<ggrid, 256>>>((const float4*)xs, (float4*)agg, N);
    gemm64_kernel<<<mgrid, 256>>>(agg, W1, dis, xs, N, 1);   // xs now holds hs

    // Layer 2
    gather_kernel<<<ggrid, 256>>>((const float4*)xs, (float4*)agg, N);
    gemm64_kernel<<<mgrid, 256>>>(agg, W2, dis, (float*)d_out, N, 0);
}

// round 4
// speedup vs baseline: 1.2171x; 1.2171x over previous
#include <cuda_runtime.h>
#include <cstdint>

// GCN 2-layer: out = spmm(relu(spmm(X)@W1))@W2,  A_norm = D^-1/2 A D^-1/2
// N=50000, E=850000, D=64.
//
// R4 = R2 structure (atomic-scatter SPMM, proven 145.5us) + packed-f32x2 GEMM.
//   xs   = dis .* X                      (prescale)
//   agg  = scatter-add xs[src] -> [dst]  (red.global.add.v4.f32, pre-zeroed)
//   hs   = relu(dis .* (agg@W1)) .* dis  (gemm epilogue: dst scale + relu + next src scale)
//   agg2 = scatter-add hs[src]
//   out  = dis .* (agg2@W2)
// GEMM uses fma.rn.f32x2 (Blackwell packed dual-FMA, ptxas never emits it):
// halves FFMA issue count and accumulator registers -> higher occupancy.

#define D 64
#define NMAX 50176

__device__ float g_xs[NMAX * D];   // prescaled features (xs, then hs)
__device__ float g_agg[NMAX * D];  // aggregation target
__device__ int g_is64;

// ---------------------------------------------------------------------------
// f32x2 helpers
// ---------------------------------------------------------------------------
__device__ __forceinline__ unsigned long long pack2(float a) {
    unsigned long long r;
    asm("mov.b64 %0, {%1, %1};" : "=l"(r) : "f"(a));
    return r;
}
__device__ __forceinline__ void fma2(unsigned long long& acc,
                                     unsigned long long a, unsigned long long b) {
    asm("fma.rn.f32x2 %0, %1, %2, %0;" : "+l"(acc) : "l"(a), "l"(b));
}
__device__ __forceinline__ float2 unpack2(unsigned long long v) {
    float2 f;
    asm("mov.b64 {%0, %1}, %2;" : "=f"(f.x), "=f"(f.y) : "l"(v));
    return f;
}

// ---------------------------------------------------------------------------
// Edge dtype detection (int64 ids < 50000 -> zero high words)
// ---------------------------------------------------------------------------
__global__ void detect_kernel(const int* __restrict__ w) {
    if (threadIdx.x == 0) {
        int is64 = 1;
        #pragma unroll 1
        for (int i = 0; i < 64; i++)
            if (w[2 * i + 1] != 0) { is64 = 0; break; }
        g_is64 = is64;
    }
}

// ---------------------------------------------------------------------------
// Prescale: xs[i,:] = dis[i] * x[i,:]
// ---------------------------------------------------------------------------
__global__ void __launch_bounds__(256) prescale_kernel(
    const float4* __restrict__ x, const float* __restrict__ dis,
    float4* __restrict__ xs, int n4)
{
    int i = blockIdx.x * 256 + threadIdx.x;
    if (i >= n4) return;
    float s = dis[i >> 4];
    float4 v = x[i];
    v.x *= s; v.y *= s; v.z *= s; v.w *= s;
    xs[i] = v;
}

// ---------------------------------------------------------------------------
// Scatter SPMM: out[dst] += feat[src]   (feat already src-scaled)
// 16 threads/edge, one float4 gather + one red.global.add.v4.f32 each.
// ---------------------------------------------------------------------------
__global__ void __launch_bounds__(256) scatter_kernel(
    const float4* __restrict__ feat,   // [N,16] float4 view
    const void*   __restrict__ ei,     // [2,E] int64 or int32
    float*        __restrict__ out,    // [N,64], pre-zeroed
    int E)
{
    int idx = blockIdx.x * 256 + threadIdx.x;
    int e = idx >> 4;
    if (e >= E) return;
    int lane = idx & 15;

    int s, d;
    if (g_is64) {
        const long long* p = (const long long*)ei;
        s = (int)p[e];
        d = (int)p[E + e];
    } else {
        const int* p = (const int*)ei;
        s = p[e];
        d = p[E + e];
    }

    float4 v = feat[s * 16 + lane];
    float* o = out + d * 64 + lane * 4;

    asm volatile("red.global.add.v4.f32 [%0], {%1, %2, %3, %4};"
                 :: "l"(o), "f"(v.x), "f"(v.y), "f"(v.z), "f"(v.w)
                 : "memory");
}

// ---------------------------------------------------------------------------
// GEMM: Y[r,:] = g(dis[r] * (X[r,:] @ W)),  W is 64x64.
//   mode 0: g(v) = v
//   mode 1: g(v) = relu(v) * dis[r]   (src-prescale for next scatter; dis>0
//                                      so relu(v*s)*s == relu-correct)
// 256 threads/CTA, 2 rows x 16 cols per thread, packed f32x2 FMA.
// ---------------------------------------------------------------------------
__global__ void __launch_bounds__(256, 3) gemm64_kernel(
    const float* __restrict__ X,
    const float* __restrict__ W,
    const float* __restrict__ dis,
    float*       __restrict__ Y,
    int n, int mode)
{
    __shared__ float Ws[64 * 64];
    #pragma unroll
    for (int i = threadIdx.x; i < 1024; i += 256)
        ((float4*)Ws)[i] = ((const float4*)W)[i];
    __syncthreads();

    int rg = threadIdx.x >> 2;          // 0..63
    int cg = (threadIdx.x & 3) << 4;    // 0,16,32,48
    int r0 = blockIdx.x * 128 + (rg << 1);

    unsigned long long acc[2][8];
    #pragma unroll
    for (int i = 0; i < 2; i++)
        #pragma unroll
        for (int j = 0; j < 8; j++)
            acc[i][j] = 0ULL;

    const float4* X4 = (const float4*)X;

    #pragma unroll 4
    for (int k4 = 0; k4 < 16; k4++) {
        float4 xv0 = (r0     < n) ? X4[ r0      * 16 + k4] : make_float4(0.f,0.f,0.f,0.f);
        float4 xv1 = (r0 + 1 < n) ? X4[(r0 + 1) * 16 + k4] : make_float4(0.f,0.f,0.f,0.f);
        #pragma unroll
        for (int kk = 0; kk < 4; kk++) {
            const unsigned long long* wrow =
                (const unsigned long long*)&Ws[(k4 * 4 + kk) * 64 + cg];
            float x0 = (kk == 0) ? xv0.x : (kk == 1) ? xv0.y : (kk == 2) ? xv0.z : xv0.w;
            float x1 = (kk == 0) ? xv1.x : (kk == 1) ? xv1.y : (kk == 2) ? xv1.z : xv1.w;
            unsigned long long p0 = pack2(x0);
            unsigned long long p1 = pack2(x1);
            #pragma unroll
            for (int j = 0; j < 8; j++) {
                unsigned long long w = wrow[j];
                fma2(acc[0][j], p0, w);
                fma2(acc[1][j], p1, w);
            }
        }
    }

    #pragma unroll
    for (int i = 0; i < 2; i++) {
        int r = r0 + i;
        if (r < n) {
            float s = dis[r];
            float* yo = &Y[r * 64 + cg];
            #pragma unroll
            for (int j4 = 0; j4 < 4; j4++) {
                float2 lo = unpack2(acc[i][j4 * 2]);
                float2 hi = unpack2(acc[i][j4 * 2 + 1]);
                float4 o;
                o.x = lo.x * s; o.y = lo.y * s;
                o.z = hi.x * s; o.w = hi.y * s;
                if (mode) {
                    o.x = fmaxf(o.x, 0.f) * s; o.y = fmaxf(o.y, 0.f) * s;
                    o.z = fmaxf(o.z, 0.f) * s; o.w = fmaxf(o.w, 0.f) * s;
                }
                *(float4*)(yo + j4 * 4) = o;
            }
        }
    }
}

// ---------------------------------------------------------------------------
// Launch
// ---------------------------------------------------------------------------
extern "C" void kernel_launch(void* const* d_in, const int* in_sizes, int n_in,
                              void* d_out, int out_size)
{
    const float* x   = (const float*)d_in[0];
    const void*  ei  = d_in[1];
    const float* dis = (const float*)d_in[2];
    const float* W1  = (const float*)d_in[n_in - 2];
    const float* W2  = (const float*)d_in[n_in - 1];

    int N = in_sizes[0] / D;
    int E = in_sizes[1] / 2;

    float* xs  = nullptr;
    float* agg = nullptr;
    cudaGetSymbolAddress((void**)&xs,  g_xs);
    cudaGetSymbolAddress((void**)&agg, g_agg);

    size_t bytes = (size_t)N * D * sizeof(float);
    int n4    = N * (D / 4);
    int pgrid = (n4 + 255) / 256;
    int sgrid = (E * 16 + 255) / 256;
    int mgrid = (N + 127) / 128;

    detect_kernel<<<1, 32>>>((const int*)ei);

    // Layer 1
    prescale_kernel<<<pgrid, 256>>>((const float4*)x, dis, (float4*)xs, n4);
    cudaMemsetAsync(agg, 0, bytes);
    scatter_kernel<<<sgrid, 256>>>((const float4*)xs, ei, agg, E);
    gemm64_kernel<<<mgrid, 256>>>(agg, W1, dis, xs, N, 1);   // xs now holds hs

    // Layer 2
    cudaMemsetAsync(agg, 0, bytes);
    scatter_kernel<<<sgrid, 256>>>((const float4*)xs, ei, agg, E);
    gemm64_kernel<<<mgrid, 256>>>(agg, W2, dis, (float*)d_out, N, 0);
}